// round 4
// baseline (speedup 1.0000x reference)
#include <cuda_runtime.h>
#include <math.h>

#define N_NODES 100000
#define N_EDGES 1280000
#define DIM 64

// Scratch (allocation-free rule: __device__ globals, zero-initialized at load).
// The GEMM kernel re-zeroes them for the next call, so no separate zero pass.
__device__ float g_agg[(size_t)N_NODES * DIM];   // 25.6 MB
__device__ float g_deg[N_NODES];

// ---------------------------------------------------------------------------
// Kernel 1: edge scatter.  4 threads per edge; each thread gathers 4 float4
// (MLP=4), scales by w, and fires 4 vector REDs.  Per warp: 8 edges with only
// 12 LSU instructions (vs 24 for the 16-thread/edge layout).
// ---------------------------------------------------------------------------
__global__ __launch_bounds__(256) void edge_kernel(
    const float* __restrict__ feat,
    const float* __restrict__ w,
    const int*   __restrict__ src,
    const int*   __restrict__ dst)
{
    unsigned t    = blockIdx.x * blockDim.x + threadIdx.x;
    unsigned e    = t >> 2;
    unsigned lane = t & 3;
    if (e >= N_EDGES) return;

    int   s  = __ldg(src + e);
    int   d  = __ldg(dst + e);
    float we = __ldg(w + e);

    // thread covers float4 slots: lane, lane+4, lane+8, lane+12 (coalesced per edge)
    const float4* fp = (const float4*)(feat + (size_t)s * DIM) + lane;
    float4 f[4];
    #pragma unroll
    for (int q = 0; q < 4; q++) f[q] = __ldg(fp + 4 * q);

    float* base = g_agg + (size_t)d * DIM + lane * 4;
    #pragma unroll
    for (int q = 0; q < 4; q++) {
        float x = f[q].x * we, y = f[q].y * we, z = f[q].z * we, v = f[q].w * we;
        asm volatile("red.global.add.v4.f32 [%0], {%1,%2,%3,%4};"
                     :: "l"(base + q * 16), "f"(x), "f"(y), "f"(z), "f"(v)
                     : "memory");
    }

    if (lane == 0) atomicAdd(g_deg + d, 1.0f);   // RED (result unused)
}

// ---------------------------------------------------------------------------
// Kernel 2: fused normalize + GEMM + scratch-reset.
//   out[r] = (agg[r] * dinv[r]) @ W
// Block: 128 rows x 64 cols, 256 threads, 8x4 register tiles.
// Hsh is stored transposed [k][row] (stride 132) so the A operand is 2x LDS.128.
// Each thread zeroes exactly the g_agg elements it alone read; g_deg is zeroed
// after the syncthreads.  This resets scratch for the next invocation.
// ---------------------------------------------------------------------------
#define TROWS 128
#define HSTRIDE 132   // 128 + 4 pad: keeps 16B alignment, conflict-free STS

__global__ __launch_bounds__(256) void norm_gemm_kernel(
    const float* __restrict__ Wm,      // [64, 64] row-major (k, c)
    float*       __restrict__ out)     // [N, 64]
{
    __shared__ float Wsh[DIM][DIM];           // W[k][c]  (16 KB)
    __shared__ float Hsh[DIM][HSTRIDE];       // H[k][row] (33 KB)

    const int tid   = threadIdx.x;
    const int rbase = blockIdx.x * TROWS;

    // Load W cooperatively (vectorized): 4096 floats / 256 threads = 4 float4.
    #pragma unroll
    for (int i = tid * 4; i < DIM * DIM; i += 256 * 4) {
        *(float4*)(&Wsh[0][0] + i) = __ldg((const float4*)(Wm + i));
    }

    // Load H tile transposed with degree normalization, then zero what we read.
    // row = tid & 127 (warp = 32 consecutive rows -> conflict-free STS),
    // segs = (tid>>7) + 2j, j=0..7  (each (row,seg) float4 has a unique owner).
    const int row = tid & 127;
    const int gr  = rbase + row;
    const bool valid = (gr < N_NODES);

    float dinv = 1.0f;
    if (valid) dinv = 1.0f / fmaxf(g_deg[gr], 1.0f);

    {
        const int seg0 = tid >> 7;                    // 0 or 1
        float4* ap = (float4*)(g_agg + (size_t)gr * DIM);
        const float4 z4 = make_float4(0.f, 0.f, 0.f, 0.f);
        #pragma unroll
        for (int j = 0; j < 8; j++) {
            const int seg = seg0 + 2 * j;             // 0..15
            float4 v = valid ? ap[seg] : z4;
            const int k = seg * 4;
            Hsh[k + 0][row] = v.x * dinv;
            Hsh[k + 1][row] = v.y * dinv;
            Hsh[k + 2][row] = v.z * dinv;
            Hsh[k + 3][row] = v.w * dinv;
            if (valid) ap[seg] = z4;                  // sole reader: reset now
        }
    }
    __syncthreads();

    // Zero degree for next call (both readers of g_deg[gr] are past the sync).
    if (tid < 128 && valid) g_deg[gr] = 0.f;

    // Compute: thread (ty,tx) owns rows 8ty..8ty+7, cols 4tx..4tx+3.
    const int ty = tid >> 4;        // 0..15
    const int tx = tid & 15;        // 0..15
    float acc[8][4] = {};

    #pragma unroll 4
    for (int k = 0; k < DIM; k++) {
        float4 a0 = *(const float4*)&Hsh[k][8 * ty];      // rows 8ty..+3
        float4 a1 = *(const float4*)&Hsh[k][8 * ty + 4];  // rows +4..+7
        float4 b  = *(const float4*)&Wsh[k][4 * tx];
        float ar[8] = {a0.x, a0.y, a0.z, a0.w, a1.x, a1.y, a1.z, a1.w};
        #pragma unroll
        for (int i = 0; i < 8; i++) {
            acc[i][0] += ar[i] * b.x;
            acc[i][1] += ar[i] * b.y;
            acc[i][2] += ar[i] * b.z;
            acc[i][3] += ar[i] * b.w;
        }
    }

    #pragma unroll
    for (int i = 0; i < 8; i++) {
        int r = rbase + 8 * ty + i;
        if (r < N_NODES) {
            *(float4*)(out + (size_t)r * DIM + 4 * tx) =
                make_float4(acc[i][0], acc[i][1], acc[i][2], acc[i][3]);
        }
    }
}

// ---------------------------------------------------------------------------
// kernel_launch: edge scatter -> fused normalize+GEMM+reset.
// Scratch starts zeroed (static zero-init on call 1; GEMM resets it for the
// next call).  Every call performs identical work -> deterministic & capturable.
// Inputs (metadata order): features, w, W, src, dst.  Output: float [N, 64].
// ---------------------------------------------------------------------------
extern "C" void kernel_launch(void* const* d_in, const int* in_sizes, int n_in,
                              void* d_out, int out_size)
{
    const float* feat = (const float*)d_in[0];
    const float* w    = (const float*)d_in[1];
    const float* Wm   = (const float*)d_in[2];
    const int*   src  = (const int*)d_in[3];
    const int*   dst  = (const int*)d_in[4];
    float*       out  = (float*)d_out;

    // edges: 4 threads per edge
    {
        long long threads = (long long)N_EDGES * 4;
        int grid = (int)((threads + 255) / 256);
        edge_kernel<<<grid, 256>>>(feat, w, src, dst);
    }
    // gemm (+ normalize + scratch reset): 128-row tiles
    {
        int grid = (N_NODES + TROWS - 1) / TROWS;
        norm_gemm_kernel<<<grid, 256>>>(Wm, out);
    }
}